// round 1
// baseline (speedup 1.0000x reference)
#include <cuda_runtime.h>
#include <math.h>

// ---------------------------------------------------------------------------
// Problem constants
// ---------------------------------------------------------------------------
#define B_  4
#define S_  2048
#define D_  1024
#define H_  16
#define DH_ 64
#define FF_ 4096
#define M_  (B_ * S_)          // 8192 rows

// ---------------------------------------------------------------------------
// Scratch (device globals: no allocation allowed)
// ---------------------------------------------------------------------------
__device__ float g_h[M_ * D_];           // ln1 / ln2 output (reused)
__device__ float g_q[M_ * D_];           // phi(q)
__device__ float g_k[M_ * D_];           // phi(k)
__device__ float g_v[M_ * D_];           // v
__device__ float g_attn[M_ * D_];        // attention output pre-WO
__device__ float g_x2[M_ * D_];          // x + attn@wo
__device__ float g_kv[B_ * H_ * DH_ * DH_];
__device__ float g_z[B_ * H_ * DH_];
__device__ float g_a1[M_ * FF_];         // lookup_act(h2 @ w1)

// ---------------------------------------------------------------------------
// Epilogue transforms
// ---------------------------------------------------------------------------
// EPI: 0 = identity, 1 = elu+1, 2 = +residual, 3 = lookup-GELU
__device__ __forceinline__ float phi_fn(float v) {
    // jax.nn.elu(v) + 1:  v>0 -> v+1 ; else exp(v)
    return v > 0.0f ? v + 1.0f : expf(v);
}

__device__ __forceinline__ float lookup_gelu(float v) {
    // idx = clip(round(v/0.1)+128, 0, 255); xq = (idx-128)*0.1; gelu_tanh(xq)
    float t = __fdiv_rn(v, 0.1f);
    float r = rintf(t);                       // round-half-even, matches jnp.round
    r = fminf(fmaxf(r, -128.0f), 127.0f);
    float xq = r * 0.1f;
    float x3 = xq * xq * xq;
    float inner = 0.7978845608028654f * (xq + 0.044715f * x3);
    return 0.5f * xq * (1.0f + tanhf(inner));
}

template <int EPI>
__device__ __forceinline__ float epi_fn(float v) {
    if (EPI == 1) return phi_fn(v);
    if (EPI == 3) return lookup_gelu(v);
    return v;
}

// ---------------------------------------------------------------------------
// SGEMM: C[M,N] = A[M,K] @ B[K,N]  (+ epilogue / residual)
// Block tile 128x128, K-tile 16, 256 threads, 8x8 per-thread micro-tile.
// M,N,K assumed multiples of the tile sizes (true for all calls here).
// ---------------------------------------------------------------------------
#define BM 128
#define BN 128
#define BK 16
#define TM 8
#define TN 8

template <int EPI>
__global__ __launch_bounds__(256, 2)
void sgemm_kernel(const float* __restrict__ A, const float* __restrict__ Bm,
                  float* __restrict__ C, const float* __restrict__ res,
                  int M, int N, int K)
{
    __shared__ float As[BK][BM];
    __shared__ float Bs[BK][BN];

    const int tid = threadIdx.x;
    const int tn = tid & 15;          // 0..15
    const int tm = tid >> 4;          // 0..15
    const int row0 = blockIdx.y * BM;
    const int col0 = blockIdx.x * BN;

    // A-tile load mapping: 512 float4 per tile; 2 per thread
    const int a_row = tid >> 2;       // 0..63 (+64)
    const int a_k4  = tid & 3;        // 0..3
    // B-tile load mapping: 512 float4; 2 per thread
    const int b_row = tid >> 5;       // 0..7 (+8)
    const int b_c4  = tid & 31;       // 0..31

    float acc[TM][TN];
    #pragma unroll
    for (int i = 0; i < TM; i++)
        #pragma unroll
        for (int j = 0; j < TN; j++) acc[i][j] = 0.0f;

    for (int k0 = 0; k0 < K; k0 += BK) {
        #pragma unroll
        for (int i = 0; i < 2; i++) {
            int r = a_row + i * 64;
            float4 va = *reinterpret_cast<const float4*>(
                &A[(size_t)(row0 + r) * K + k0 + a_k4 * 4]);
            As[a_k4 * 4 + 0][r] = va.x;
            As[a_k4 * 4 + 1][r] = va.y;
            As[a_k4 * 4 + 2][r] = va.z;
            As[a_k4 * 4 + 3][r] = va.w;
        }
        #pragma unroll
        for (int i = 0; i < 2; i++) {
            int r = b_row + i * 8;
            *reinterpret_cast<float4*>(&Bs[r][b_c4 * 4]) =
                *reinterpret_cast<const float4*>(
                    &Bm[(size_t)(k0 + r) * N + col0 + b_c4 * 4]);
        }
        __syncthreads();

        #pragma unroll
        for (int kk = 0; kk < BK; kk++) {
            float af[TM], bf[TN];
            #pragma unroll
            for (int i = 0; i < TM; i += 4)
                *reinterpret_cast<float4*>(&af[i]) =
                    *reinterpret_cast<const float4*>(&As[kk][tm * TM + i]);
            #pragma unroll
            for (int j = 0; j < TN; j += 4)
                *reinterpret_cast<float4*>(&bf[j]) =
                    *reinterpret_cast<const float4*>(&Bs[kk][tn * TN + j]);
            #pragma unroll
            for (int i = 0; i < TM; i++)
                #pragma unroll
                for (int j = 0; j < TN; j++)
                    acc[i][j] += af[i] * bf[j];
        }
        __syncthreads();
    }

    // Epilogue
    #pragma unroll
    for (int i = 0; i < TM; i++) {
        size_t r = (size_t)(row0 + tm * TM + i);
        float* crow = C + r * N + col0 + tn * TN;
        const float* rrow = (EPI == 2) ? (res + r * N + col0 + tn * TN) : nullptr;
        #pragma unroll
        for (int j = 0; j < TN; j += 4) {
            float4 o;
            o.x = epi_fn<EPI>(acc[i][j + 0]);
            o.y = epi_fn<EPI>(acc[i][j + 1]);
            o.z = epi_fn<EPI>(acc[i][j + 2]);
            o.w = epi_fn<EPI>(acc[i][j + 3]);
            if (EPI == 2) {
                float4 rv = *reinterpret_cast<const float4*>(&rrow[j]);
                o.x += rv.x; o.y += rv.y; o.z += rv.z; o.w += rv.w;
            }
            *reinterpret_cast<float4*>(&crow[j]) = o;
        }
    }
}

// ---------------------------------------------------------------------------
// LayerNorm: one block (256 threads) per row of 1024
// ---------------------------------------------------------------------------
__global__ __launch_bounds__(256)
void ln_kernel(const float* __restrict__ x, const float* __restrict__ g,
               const float* __restrict__ bb, float* __restrict__ y)
{
    __shared__ float red[8];
    const int row = blockIdx.x;
    const int tid = threadIdx.x;
    const float4* xr = reinterpret_cast<const float4*>(x + (size_t)row * D_);
    float4 v = xr[tid];

    float s = v.x + v.y + v.z + v.w;
    #pragma unroll
    for (int o = 16; o > 0; o >>= 1) s += __shfl_xor_sync(0xffffffffu, s, o);
    if ((tid & 31) == 0) red[tid >> 5] = s;
    __syncthreads();
    s = 0.0f;
    #pragma unroll
    for (int i = 0; i < 8; i++) s += red[i];
    const float mean = s * (1.0f / D_);
    __syncthreads();

    float d0 = v.x - mean, d1 = v.y - mean, d2 = v.z - mean, d3 = v.w - mean;
    float s2 = d0 * d0 + d1 * d1 + d2 * d2 + d3 * d3;
    #pragma unroll
    for (int o = 16; o > 0; o >>= 1) s2 += __shfl_xor_sync(0xffffffffu, s2, o);
    if ((tid & 31) == 0) red[tid >> 5] = s2;
    __syncthreads();
    s2 = 0.0f;
    #pragma unroll
    for (int i = 0; i < 8; i++) s2 += red[i];
    const float var = s2 * (1.0f / D_);
    const float rs = 1.0f / sqrtf(var + 1e-5f);

    float4 gg = reinterpret_cast<const float4*>(g)[tid];
    float4 bv = reinterpret_cast<const float4*>(bb)[tid];
    float4 o;
    o.x = d0 * rs * gg.x + bv.x;
    o.y = d1 * rs * gg.y + bv.y;
    o.z = d2 * rs * gg.z + bv.z;
    o.w = d3 * rs * gg.w + bv.w;
    reinterpret_cast<float4*>(y + (size_t)row * D_)[tid] = o;
}

// ---------------------------------------------------------------------------
// kv[b,h,d,e] = sum_s phi_k[b,s,h,d] * v[b,s,h,e];  z[b,h,d] = sum_s phi_k
// One block (256 threads) per (b,h). Each thread computes a 4x4 micro-tile.
// ---------------------------------------------------------------------------
__global__ __launch_bounds__(256)
void kv_kernel(const float* __restrict__ k, const float* __restrict__ v,
               float* __restrict__ kv, float* __restrict__ z)
{
    const int bh = blockIdx.x;           // 0..63
    const int b = bh >> 4, h = bh & 15;
    const float* Kp = k + (size_t)b * S_ * D_ + h * DH_;
    const float* Vp = v + (size_t)b * S_ * D_ + h * DH_;

    __shared__ float Ks[32][DH_];
    __shared__ float Vs[32][DH_];

    const int tid = threadIdx.x;
    const int tx = tid & 15, ty = tid >> 4;

    float acc[4][4];
    #pragma unroll
    for (int i = 0; i < 4; i++)
        #pragma unroll
        for (int j = 0; j < 4; j++) acc[i][j] = 0.0f;
    float zacc = 0.0f;

    for (int s0 = 0; s0 < S_; s0 += 32) {
        #pragma unroll
        for (int i = 0; i < 2; i++) {
            int jj = tid * 2 + i;
            int r = jj >> 4;
            int c4 = jj & 15;
            *reinterpret_cast<float4*>(&Ks[r][c4 * 4]) =
                *reinterpret_cast<const float4*>(&Kp[(size_t)(s0 + r) * D_ + c4 * 4]);
            *reinterpret_cast<float4*>(&Vs[r][c4 * 4]) =
                *reinterpret_cast<const float4*>(&Vp[(size_t)(s0 + r) * D_ + c4 * 4]);
        }
        __syncthreads();

        #pragma unroll 8
        for (int s = 0; s < 32; s++) {
            float a[4], bbv[4];
            *reinterpret_cast<float4*>(a) =
                *reinterpret_cast<const float4*>(&Ks[s][ty * 4]);
            *reinterpret_cast<float4*>(bbv) =
                *reinterpret_cast<const float4*>(&Vs[s][tx * 4]);
            #pragma unroll
            for (int i = 0; i < 4; i++)
                #pragma unroll
                for (int j = 0; j < 4; j++)
                    acc[i][j] += a[i] * bbv[j];
        }
        if (tid < DH_) {
            #pragma unroll 8
            for (int s = 0; s < 32; s++) zacc += Ks[s][tid];
        }
        __syncthreads();
    }

    float* kvp = kv + (size_t)bh * DH_ * DH_;
    #pragma unroll
    for (int i = 0; i < 4; i++)
        #pragma unroll
        for (int j = 0; j < 4; j++)
            kvp[(ty * 4 + i) * DH_ + tx * 4 + j] = acc[i][j];
    if (tid < DH_) z[bh * DH_ + tid] = zacc;
}

// ---------------------------------------------------------------------------
// num/den: out[s,:] = (phi_q[s,:] @ kv) / (phi_q[s,:] . z + 1e-6)
// Grid (bh, s-chunk of 128). 128 threads, one row each.
// ---------------------------------------------------------------------------
__global__ __launch_bounds__(128)
void attn_kernel(const float* __restrict__ q, const float* __restrict__ kv,
                 const float* __restrict__ z, float* __restrict__ out)
{
    const int bh = blockIdx.x;
    const int b = bh >> 4, h = bh & 15;
    __shared__ float kvs[DH_ * DH_];
    __shared__ float zs[DH_];
    const int tid = threadIdx.x;

    const float4* kvg = reinterpret_cast<const float4*>(kv + (size_t)bh * DH_ * DH_);
    #pragma unroll
    for (int i = 0; i < 8; i++)
        reinterpret_cast<float4*>(kvs)[tid + i * 128] = kvg[tid + i * 128];
    if (tid < 16)
        reinterpret_cast<float4*>(zs)[tid] =
            reinterpret_cast<const float4*>(z + bh * DH_)[tid];
    __syncthreads();

    const int s = blockIdx.y * 128 + tid;
    const float* qr = q + (size_t)(b * S_ + s) * D_ + h * DH_;
    float pq[DH_];
    #pragma unroll
    for (int i = 0; i < 16; i++)
        reinterpret_cast<float4*>(pq)[i] = reinterpret_cast<const float4*>(qr)[i];

    float acc[DH_];
    #pragma unroll
    for (int e = 0; e < DH_; e++) acc[e] = 0.0f;
    float den = 1e-6f;

    #pragma unroll 8
    for (int d = 0; d < DH_; d++) {
        float a = pq[d];
        den += a * zs[d];
        const float4* kr = reinterpret_cast<const float4*>(&kvs[d * DH_]);
        #pragma unroll
        for (int e4 = 0; e4 < 16; e4++) {
            float4 kk = kr[e4];
            acc[e4 * 4 + 0] += a * kk.x;
            acc[e4 * 4 + 1] += a * kk.y;
            acc[e4 * 4 + 2] += a * kk.z;
            acc[e4 * 4 + 3] += a * kk.w;
        }
    }

    const float inv = __fdiv_rn(1.0f, den);
    float* orow = out + (size_t)(b * S_ + s) * D_ + h * DH_;
    #pragma unroll
    for (int i = 0; i < 16; i++) {
        float4 o;
        o.x = acc[i * 4 + 0] * inv;
        o.y = acc[i * 4 + 1] * inv;
        o.z = acc[i * 4 + 2] * inv;
        o.w = acc[i * 4 + 3] * inv;
        reinterpret_cast<float4*>(orow)[i] = o;
    }
}

// ---------------------------------------------------------------------------
// Launch
// ---------------------------------------------------------------------------
extern "C" void kernel_launch(void* const* d_in, const int* in_sizes, int n_in,
                              void* d_out, int out_size)
{
    const float* x    = (const float*)d_in[0];
    const float* ln1g = (const float*)d_in[1];
    const float* ln1b = (const float*)d_in[2];
    const float* wq   = (const float*)d_in[3];
    const float* wk   = (const float*)d_in[4];
    const float* wv   = (const float*)d_in[5];
    const float* wo   = (const float*)d_in[6];
    const float* ln2g = (const float*)d_in[7];
    const float* ln2b = (const float*)d_in[8];
    const float* w1   = (const float*)d_in[9];
    const float* w2   = (const float*)d_in[10];
    float* out = (float*)d_out;

    float *h, *q, *k, *v, *attn, *x2, *kv, *z, *a1;
    cudaGetSymbolAddress((void**)&h,    g_h);
    cudaGetSymbolAddress((void**)&q,    g_q);
    cudaGetSymbolAddress((void**)&k,    g_k);
    cudaGetSymbolAddress((void**)&v,    g_v);
    cudaGetSymbolAddress((void**)&attn, g_attn);
    cudaGetSymbolAddress((void**)&x2,   g_x2);
    cudaGetSymbolAddress((void**)&kv,   g_kv);
    cudaGetSymbolAddress((void**)&z,    g_z);
    cudaGetSymbolAddress((void**)&a1,   g_a1);

    // 1. h = LN1(x)
    ln_kernel<<<M_, 256>>>(x, ln1g, ln1b, h);

    // 2. q/k/v = h @ {wq,wk,wv}; phi applied to q,k in epilogue
    dim3 gD(D_ / BN, M_ / BM);
    sgemm_kernel<1><<<gD, 256>>>(h, wq, q, nullptr, M_, D_, D_);
    sgemm_kernel<1><<<gD, 256>>>(h, wk, k, nullptr, M_, D_, D_);
    sgemm_kernel<0><<<gD, 256>>>(h, wv, v, nullptr, M_, D_, D_);

    // 3. kv/z reductions per (b,h)
    kv_kernel<<<B_ * H_, 256>>>(k, v, kv, z);

    // 4. attn = (phi_q @ kv) / (phi_q . z + 1e-6)
    attn_kernel<<<dim3(B_ * H_, S_ / 128), 128>>>(q, kv, z, attn);

    // 5. x2 = x + attn @ wo
    sgemm_kernel<2><<<gD, 256>>>(attn, wo, x2, x, M_, D_, D_);

    // 6. h = LN2(x2)
    ln_kernel<<<M_, 256>>>(x2, ln2g, ln2b, h);

    // 7. a1 = lookup_act(h @ w1)
    dim3 gF(FF_ / BN, M_ / BM);
    sgemm_kernel<3><<<gF, 256>>>(h, w1, a1, nullptr, M_, FF_, D_);

    // 8. out = x2 + a1 @ w2
    sgemm_kernel<2><<<gD, 256>>>(a1, w2, out, x2, M_, D_, FF_);
}

// round 3
// speedup vs baseline: 3.4047x; 3.4047x over previous
#include <cuda_runtime.h>
#include <cuda_bf16.h>
#include <math.h>
#include <stdint.h>

// ---------------------------------------------------------------------------
// Problem constants
// ---------------------------------------------------------------------------
#define B_  4
#define S_  2048
#define D_  1024
#define H_  16
#define DH_ 64
#define FF_ 4096
#define M_  (B_ * S_)          // 8192 rows

// ---------------------------------------------------------------------------
// Scratch (device globals)
// ---------------------------------------------------------------------------
__device__ __nv_bfloat16 g_h2[M_ * 2 * D_];          // LN output, split (hi | lo)
__device__ __nv_bfloat16 g_attn2[M_ * 2 * D_];       // attention output, split
__device__ __nv_bfloat16 g_a1[(size_t)M_ * 2 * FF_]; // lookup out, split
__device__ float g_q[M_ * D_];
__device__ float g_k[M_ * D_];
__device__ float g_v[M_ * D_];
__device__ float g_x2[M_ * D_];
__device__ float g_kv[B_ * H_ * DH_ * DH_];
__device__ float g_z[B_ * H_ * DH_];
// transposed bf16 weights (K-major rows: wt[n,k] = w[k,n])
__device__ __nv_bfloat16 g_wqt[D_ * D_];
__device__ __nv_bfloat16 g_wkt[D_ * D_];
__device__ __nv_bfloat16 g_wvt[D_ * D_];
__device__ __nv_bfloat16 g_wot[D_ * D_];
__device__ __nv_bfloat16 g_w1t[FF_ * D_];
__device__ __nv_bfloat16 g_w2t[D_ * FF_];

// ---------------------------------------------------------------------------
// PTX helpers (portable ISA only: cp.async, ldmatrix, mma.sync)
// ---------------------------------------------------------------------------
__device__ __forceinline__ uint32_t smem_u32(const void* p) {
    uint32_t a;
    asm("{ .reg .u64 t; cvta.to.shared.u64 t, %1; cvt.u32.u64 %0, t; }"
        : "=r"(a) : "l"(p));
    return a;
}
__device__ __forceinline__ void cp_async16(uint32_t dst, const void* src) {
    asm volatile("cp.async.cg.shared.global [%0], [%1], 16;" :: "r"(dst), "l"(src));
}
#define CP_COMMIT() asm volatile("cp.async.commit_group;" ::: "memory")
template <int N>
__device__ __forceinline__ void cp_wait() {
    asm volatile("cp.async.wait_group %0;" :: "n"(N) : "memory");
}
__device__ __forceinline__ void ldm_x4(uint32_t& r0, uint32_t& r1, uint32_t& r2,
                                       uint32_t& r3, uint32_t addr) {
    asm volatile("ldmatrix.sync.aligned.m8n8.x4.shared.b16 {%0,%1,%2,%3}, [%4];"
                 : "=r"(r0), "=r"(r1), "=r"(r2), "=r"(r3) : "r"(addr));
}
__device__ __forceinline__ void mma_bf16(float& c0, float& c1, float& c2, float& c3,
                                         uint32_t a0, uint32_t a1, uint32_t a2,
                                         uint32_t a3, uint32_t b0, uint32_t b1) {
    asm volatile(
        "mma.sync.aligned.m16n8k16.row.col.f32.bf16.bf16.f32 "
        "{%0,%1,%2,%3}, {%4,%5,%6,%7}, {%8,%9}, {%0,%1,%2,%3};"
        : "+f"(c0), "+f"(c1), "+f"(c2), "+f"(c3)
        : "r"(a0), "r"(a1), "r"(a2), "r"(a3), "r"(b0), "r"(b1));
}
// SW128 xor swizzle on byte offsets (rows of 128B)
__device__ __forceinline__ uint32_t swz(uint32_t o) { return o ^ ((o >> 3) & 0x70u); }

// ---------------------------------------------------------------------------
// Math helpers
// ---------------------------------------------------------------------------
__device__ __forceinline__ float phi_fn(float v) {
    return v > 0.0f ? v + 1.0f : expf(v);
}
__device__ __forceinline__ float lookup_gelu(float v) {
    float r = rintf(__fdiv_rn(v, 0.1f));
    r = fminf(fmaxf(r, -128.0f), 127.0f);
    float xq = r * 0.1f;
    float inner = 0.7978845608028654f * (xq + 0.044715f * xq * xq * xq);
    return 0.5f * xq * (1.0f + tanhf(inner));
}
__device__ __forceinline__ void split_bf16(float v, __nv_bfloat16& hi, __nv_bfloat16& lo) {
    hi = __float2bfloat16_rn(v);
    lo = __float2bfloat16_rn(v - __bfloat162float(hi));
}

// ---------------------------------------------------------------------------
// bf16 split GEMM via mma.sync:
//   C[M,Ntot] = Ahi @ W^T + Alo @ W^T
//   A2 bf16 [M, 2K] (hi | lo), Bt bf16 [Ntot, K] (K-major)
// Tile 128x128, BK=64, 3-stage cp.async, 256 threads, warp tile 64x32.
// EPI: 0 identity->f32, 1 phi->f32, 2 +res->f32, 3 lookup->bf16 split
// ---------------------------------------------------------------------------
#define GBM 128
#define GBN 128
#define KC  64                       // bf16 elements per k-chunk (128 bytes)
#define TILE_BYTES (128 * 128)       // one 128-row x 128B tile = 16 KB
#define STG_BYTES (3 * TILE_BYTES)   // B | A_hi | A_lo = 48 KB
#define OFF_B  0
#define OFF_AH TILE_BYTES
#define OFF_AL (2 * TILE_BYTES)
#define NSTG 3
#define SMEM_TOTAL (NSTG * STG_BYTES)

template <int EPI>
__global__ __launch_bounds__(256, 1)
void mma_gemm(const __nv_bfloat16* __restrict__ A2, const __nv_bfloat16* __restrict__ Bt,
              int K, int Ntot, const float* __restrict__ res,
              float* __restrict__ outF, __nv_bfloat16* __restrict__ outS)
{
    extern __shared__ char smem[];
    const uint32_t sb = smem_u32(smem);
    const int tid = threadIdx.x;
    const int wid = tid >> 5;
    const int lane = tid & 31;
    const int wr = wid >> 2;          // 0..1 : warp row (64 rows)
    const int wc = wid & 3;           // 0..3 : warp col (32 cols)
    const int row0 = blockIdx.y * GBM;
    const int col0 = blockIdx.x * GBN;
    const int lda = 2 * K;
    const int C = K / KC;

    // ldmatrix address components (within-tile, before stage base)
    const int g = lane >> 3;          // address group 0..3
    const int l8 = lane & 7;
    // A (per ma): rows wr*64 + ma*16 + (g&1)*8 + l8 ; k-byte (g>>1)*16 (+ks*32)
    const int a_row = wr * 64 + (g & 1) * 8 + l8;
    const int a_kb  = (g >> 1) * 16;
    // B (per nb covering n-atoms 2nb,2nb+1): rows wc*32 + nb*16 + (g>>1)*8 + l8 ;
    // k-byte (g&1)*16 (+ks*32)
    const int b_row = wc * 32 + (g >> 1) * 8 + l8;
    const int b_kb  = (g & 1) * 16;

    float acc[4][4][4];
    #pragma unroll
    for (int i = 0; i < 4; i++)
        #pragma unroll
        for (int j = 0; j < 4; j++)
            #pragma unroll
            for (int t = 0; t < 4; t++) acc[i][j][t] = 0.0f;

    auto load_chunk = [&](int c, int s) {
        const uint32_t st = sb + s * STG_BYTES;
        const int k0 = c * KC;
        #pragma unroll
        for (int i = 0; i < 4; ++i) {
            int seg = i * 256 + tid;       // 0..1023
            int r = seg >> 3, c8 = seg & 7;
            uint32_t doff = swz(r * 128 + c8 * 16);
            const __nv_bfloat16* bsrc = Bt + (size_t)(col0 + r) * K + k0 + c8 * 8;
            cp_async16(st + OFF_B + doff, bsrc);
            const __nv_bfloat16* ah = A2 + (size_t)(row0 + r) * lda + k0 + c8 * 8;
            cp_async16(st + OFF_AH + doff, ah);
            cp_async16(st + OFF_AL + doff, ah + K);
        }
        CP_COMMIT();
    };

    load_chunk(0, 0);
    if (C > 1) load_chunk(1, 1);
    if (C > 2) load_chunk(2, 2);

    for (int c = 0; c < C; ++c) {
        const int s = c % NSTG;
        if (c + 3 <= C) cp_wait<2>();
        else if (c + 2 == C) cp_wait<1>();
        else cp_wait<0>();
        __syncthreads();

        const uint32_t st = sb + s * STG_BYTES;
        const uint32_t ab = st + OFF_AH;
        const uint32_t alb = st + OFF_AL;
        const uint32_t bb = st + OFF_B;

        #pragma unroll
        for (int ks = 0; ks < 4; ++ks) {
            const int kb = ks * 32;
            // B fragments: 4 n-atoms (2 x ldmatrix.x4)
            uint32_t bf[4][2];
            #pragma unroll
            for (int nb = 0; nb < 2; ++nb) {
                uint32_t addr = bb + swz((b_row + nb * 16) * 128 + kb + b_kb);
                ldm_x4(bf[nb * 2][0], bf[nb * 2][1],
                       bf[nb * 2 + 1][0], bf[nb * 2 + 1][1], addr);
            }
            // A hi
            #pragma unroll
            for (int ma = 0; ma < 4; ++ma) {
                uint32_t a0, a1, a2, a3;
                ldm_x4(a0, a1, a2, a3,
                       ab + swz((a_row + ma * 16) * 128 + kb + a_kb));
                #pragma unroll
                for (int na = 0; na < 4; ++na)
                    mma_bf16(acc[ma][na][0], acc[ma][na][1],
                             acc[ma][na][2], acc[ma][na][3],
                             a0, a1, a2, a3, bf[na][0], bf[na][1]);
            }
            // A lo
            #pragma unroll
            for (int ma = 0; ma < 4; ++ma) {
                uint32_t a0, a1, a2, a3;
                ldm_x4(a0, a1, a2, a3,
                       alb + swz((a_row + ma * 16) * 128 + kb + a_kb));
                #pragma unroll
                for (int na = 0; na < 4; ++na)
                    mma_bf16(acc[ma][na][0], acc[ma][na][1],
                             acc[ma][na][2], acc[ma][na][3],
                             a0, a1, a2, a3, bf[na][0], bf[na][1]);
            }
        }
        __syncthreads();
        if (c + 3 < C) load_chunk(c + 3, s);
    }

    // Epilogue: acc[ma][na][t]: c0,c1 at (m = ma*16 + lane/4 [, +8 for c2,c3]),
    // cols n = na*8 + (lane%4)*2 (+1)
    const int er = row0 + wr * 64 + (lane >> 2);
    const int ec = col0 + wc * 32 + (lane & 3) * 2;
    #pragma unroll
    for (int ma = 0; ma < 4; ++ma) {
        #pragma unroll
        for (int na = 0; na < 4; ++na) {
            const int r0r = er + ma * 16;
            const int cc = ec + na * 8;
            if (EPI == 3) {
                #pragma unroll
                for (int half = 0; half < 2; ++half) {
                    const int rr = r0r + half * 8;
                    float v0 = lookup_gelu(acc[ma][na][half * 2 + 0]);
                    float v1 = lookup_gelu(acc[ma][na][half * 2 + 1]);
                    __nv_bfloat16 h0, l0, h1, l1;
                    split_bf16(v0, h0, l0);
                    split_bf16(v1, h1, l1);
                    __nv_bfloat162 hp; hp.x = h0; hp.y = h1;
                    __nv_bfloat162 lp; lp.x = l0; lp.y = l1;
                    size_t base = (size_t)rr * (2 * Ntot) + cc;
                    *reinterpret_cast<__nv_bfloat162*>(outS + base) = hp;
                    *reinterpret_cast<__nv_bfloat162*>(outS + base + Ntot) = lp;
                }
            } else {
                #pragma unroll
                for (int half = 0; half < 2; ++half) {
                    const int rr = r0r + half * 8;
                    float v0 = acc[ma][na][half * 2 + 0];
                    float v1 = acc[ma][na][half * 2 + 1];
                    if (EPI == 1) { v0 = phi_fn(v0); v1 = phi_fn(v1); }
                    float* op = outF + (size_t)rr * Ntot + cc;
                    if (EPI == 2) {
                        const float2 rv = *reinterpret_cast<const float2*>(
                            res + (size_t)rr * Ntot + cc);
                        v0 += rv.x; v1 += rv.y;
                    }
                    float2 o; o.x = v0; o.y = v1;
                    *reinterpret_cast<float2*>(op) = o;
                }
            }
        }
    }
}

// ---------------------------------------------------------------------------
// Weight transpose + bf16 convert: wt[n,k] = bf16(w[k,n])
// ---------------------------------------------------------------------------
__global__ __launch_bounds__(256)
void transpose_bf16(const float* __restrict__ w, __nv_bfloat16* __restrict__ wt,
                    int K, int N)
{
    __shared__ float t[32][33];
    const int tx = threadIdx.x & 31, ty = threadIdx.x >> 5;  // 32 x 8
    const int k0 = blockIdx.x * 32, n0 = blockIdx.y * 32;
    #pragma unroll
    for (int i = 0; i < 4; ++i)
        t[ty + i * 8][tx] = w[(size_t)(k0 + ty + i * 8) * N + n0 + tx];
    __syncthreads();
    #pragma unroll
    for (int i = 0; i < 4; ++i)
        wt[(size_t)(n0 + ty + i * 8) * K + k0 + tx] =
            __float2bfloat16_rn(t[tx][ty + i * 8]);
}

// ---------------------------------------------------------------------------
// LayerNorm -> split bf16 [M, 2*D]
// ---------------------------------------------------------------------------
__global__ __launch_bounds__(256)
void ln_split_kernel(const float* __restrict__ x, const float* __restrict__ g,
                     const float* __restrict__ bb, __nv_bfloat16* __restrict__ y2)
{
    __shared__ float red[8];
    const int row = blockIdx.x;
    const int tid = threadIdx.x;
    float4 v = reinterpret_cast<const float4*>(x + (size_t)row * D_)[tid];

    float s = v.x + v.y + v.z + v.w;
    #pragma unroll
    for (int o = 16; o > 0; o >>= 1) s += __shfl_xor_sync(0xffffffffu, s, o);
    if ((tid & 31) == 0) red[tid >> 5] = s;
    __syncthreads();
    s = 0.0f;
    #pragma unroll
    for (int i = 0; i < 8; i++) s += red[i];
    const float mean = s * (1.0f / D_);
    __syncthreads();

    float d0 = v.x - mean, d1 = v.y - mean, d2 = v.z - mean, d3 = v.w - mean;
    float s2 = d0 * d0 + d1 * d1 + d2 * d2 + d3 * d3;
    #pragma unroll
    for (int o = 16; o > 0; o >>= 1) s2 += __shfl_xor_sync(0xffffffffu, s2, o);
    if ((tid & 31) == 0) red[tid >> 5] = s2;
    __syncthreads();
    s2 = 0.0f;
    #pragma unroll
    for (int i = 0; i < 8; i++) s2 += red[i];
    const float rs = rsqrtf(s2 * (1.0f / D_) + 1e-5f);

    float4 gg = reinterpret_cast<const float4*>(g)[tid];
    float4 bv = reinterpret_cast<const float4*>(bb)[tid];
    float o0 = d0 * rs * gg.x + bv.x;
    float o1 = d1 * rs * gg.y + bv.y;
    float o2 = d2 * rs * gg.z + bv.z;
    float o3 = d3 * rs * gg.w + bv.w;

    size_t base = (size_t)row * (2 * D_) + tid * 4;
    __nv_bfloat16 h0, l0, h1, l1, h2, l2, h3, l3;
    split_bf16(o0, h0, l0); split_bf16(o1, h1, l1);
    split_bf16(o2, h2, l2); split_bf16(o3, h3, l3);
    __nv_bfloat162 hp0; hp0.x = h0; hp0.y = h1;
    __nv_bfloat162 hp1; hp1.x = h2; hp1.y = h3;
    __nv_bfloat162 lp0; lp0.x = l0; lp0.y = l1;
    __nv_bfloat162 lp1; lp1.x = l2; lp1.y = l3;
    *reinterpret_cast<__nv_bfloat162*>(y2 + base) = hp0;
    *reinterpret_cast<__nv_bfloat162*>(y2 + base + 2) = hp1;
    *reinterpret_cast<__nv_bfloat162*>(y2 + base + D_) = lp0;
    *reinterpret_cast<__nv_bfloat162*>(y2 + base + D_ + 2) = lp1;
}

// ---------------------------------------------------------------------------
// kv[b,h,d,e] = sum_s phi_k * v ; z[b,h,d] = sum_s phi_k   (fp32)
// ---------------------------------------------------------------------------
__global__ __launch_bounds__(256)
void kv_kernel(const float* __restrict__ k, const float* __restrict__ v,
               float* __restrict__ kv, float* __restrict__ z)
{
    const int bh = blockIdx.x;
    const int b = bh >> 4, h = bh & 15;
    const float* Kp = k + (size_t)b * S_ * D_ + h * DH_;
    const float* Vp = v + (size_t)b * S_ * D_ + h * DH_;

    __shared__ float Ks[32][DH_];
    __shared__ float Vs[32][DH_];

    const int tid = threadIdx.x;
    const int tx = tid & 15, ty = tid >> 4;

    float acc[4][4];
    #pragma unroll
    for (int i = 0; i < 4; i++)
        #pragma unroll
        for (int j = 0; j < 4; j++) acc[i][j] = 0.0f;
    float zacc = 0.0f;

    for (int s0 = 0; s0 < S_; s0 += 32) {
        #pragma unroll
        for (int i = 0; i < 2; i++) {
            int jj = tid * 2 + i;
            int r = jj >> 4, c4 = jj & 15;
            *reinterpret_cast<float4*>(&Ks[r][c4 * 4]) =
                *reinterpret_cast<const float4*>(&Kp[(size_t)(s0 + r) * D_ + c4 * 4]);
            *reinterpret_cast<float4*>(&Vs[r][c4 * 4]) =
                *reinterpret_cast<const float4*>(&Vp[(size_t)(s0 + r) * D_ + c4 * 4]);
        }
        __syncthreads();
        #pragma unroll 8
        for (int s = 0; s < 32; s++) {
            float a[4], bv[4];
            *reinterpret_cast<float4*>(a) = *reinterpret_cast<const float4*>(&Ks[s][ty * 4]);
            *reinterpret_cast<float4*>(bv) = *reinterpret_cast<const float4*>(&Vs[s][tx * 4]);
            #pragma unroll
            for (int i = 0; i < 4; i++)
                #pragma unroll
                for (int j = 0; j < 4; j++) acc[i][j] += a[i] * bv[j];
        }
        if (tid < DH_) {
            #pragma unroll 8
            for (int s = 0; s < 32; s++) zacc += Ks[s][tid];
        }
        __syncthreads();
    }

    float* kvp = kv + (size_t)bh * DH_ * DH_;
    #pragma unroll
    for (int i = 0; i < 4; i++)
        #pragma unroll
        for (int j = 0; j < 4; j++)
            kvp[(ty * 4 + i) * DH_ + tx * 4 + j] = acc[i][j];
    if (tid < DH_) z[bh * DH_ + tid] = zacc;
}

// ---------------------------------------------------------------------------
// attn out row = (phi_q @ kv) / (phi_q . z + 1e-6)  -> split bf16 [M, 2*D]
// ---------------------------------------------------------------------------
__global__ __launch_bounds__(128)
void attn_kernel(const float* __restrict__ q, const float* __restrict__ kv,
                 const float* __restrict__ z, __nv_bfloat16* __restrict__ out2)
{
    const int bh = blockIdx.x;
    const int b = bh >> 4, h = bh & 15;
    __shared__ float kvs[DH_ * DH_];
    __shared__ float zs[DH_];
    const int tid = threadIdx.x;

    const float4* kvg = reinterpret_cast<const float4*>(kv + (size_t)bh * DH_ * DH_);
    #pragma unroll
    for (int i = 0; i < 8; i++)
        reinterpret_cast<float4*>(kvs)[tid + i * 128] = kvg[tid + i * 128];
    if (tid < 16)
        reinterpret_cast<float4*>(zs)[tid] =
            reinterpret_cast<const float4*>(z + bh * DH_)[tid];
    __syncthreads();

    const int s = blockIdx.y * 128 + tid;
    const float* qr = q + (size_t)(b * S_ + s) * D_ + h * DH_;
    float pq[DH_];
    #pragma unroll
    for (int i = 0; i < 16; i++)
        reinterpret_cast<float4*>(pq)[i] = reinterpret_cast<const float4*>(qr)[i];

    float acc[DH_];
    #pragma unroll
    for (int e = 0; e < DH_; e++) acc[e] = 0.0f;
    float den = 1e-6f;

    #pragma unroll 8
    for (int d = 0; d < DH_; d++) {
        float a = pq[d];
        den += a * zs[d];
        const float4* kr = reinterpret_cast<const float4*>(&kvs[d * DH_]);
        #pragma unroll
        for (int e4 = 0; e4 < 16; e4++) {
            float4 kk = kr[e4];
            acc[e4 * 4 + 0] += a * kk.x;
            acc[e4 * 4 + 1] += a * kk.y;
            acc[e4 * 4 + 2] += a * kk.z;
            acc[e4 * 4 + 3] += a * kk.w;
        }
    }

    const float inv = __fdiv_rn(1.0f, den);
    size_t base = (size_t)(b * S_ + s) * (2 * D_) + h * DH_;
    #pragma unroll
    for (int e = 0; e < DH_; e += 2) {
        __nv_bfloat16 h0, l0, h1, l1;
        split_bf16(acc[e] * inv, h0, l0);
        split_bf16(acc[e + 1] * inv, h1, l1);
        __nv_bfloat162 hp; hp.x = h0; hp.y = h1;
        __nv_bfloat162 lp; lp.x = l0; lp.y = l1;
        *reinterpret_cast<__nv_bfloat162*>(out2 + base + e) = hp;
        *reinterpret_cast<__nv_bfloat162*>(out2 + base + D_ + e) = lp;
    }
}

// ---------------------------------------------------------------------------
// Launch
// ---------------------------------------------------------------------------
extern "C" void kernel_launch(void* const* d_in, const int* in_sizes, int n_in,
                              void* d_out, int out_size)
{
    const float* x    = (const float*)d_in[0];
    const float* ln1g = (const float*)d_in[1];
    const float* ln1b = (const float*)d_in[2];
    const float* wq   = (const float*)d_in[3];
    const float* wk   = (const float*)d_in[4];
    const float* wv   = (const float*)d_in[5];
    const float* wo   = (const float*)d_in[6];
    const float* ln2g = (const float*)d_in[7];
    const float* ln2b = (const float*)d_in[8];
    const float* w1   = (const float*)d_in[9];
    const float* w2   = (const float*)d_in[10];
    float* out = (float*)d_out;

    __nv_bfloat16 *h2, *attn2, *a1, *wqt, *wkt, *wvt, *wot, *w1t, *w2t;
    float *q, *k, *v, *x2, *kvp, *zp;
    cudaGetSymbolAddress((void**)&h2,    g_h2);
    cudaGetSymbolAddress((void**)&attn2, g_attn2);
    cudaGetSymbolAddress((void**)&a1,    g_a1);
    cudaGetSymbolAddress((void**)&wqt,   g_wqt);
    cudaGetSymbolAddress((void**)&wkt,   g_wkt);
    cudaGetSymbolAddress((void**)&wvt,   g_wvt);
    cudaGetSymbolAddress((void**)&wot,   g_wot);
    cudaGetSymbolAddress((void**)&w1t,   g_w1t);
    cudaGetSymbolAddress((void**)&w2t,   g_w2t);
    cudaGetSymbolAddress((void**)&q,     g_q);
    cudaGetSymbolAddress((void**)&k,     g_k);
    cudaGetSymbolAddress((void**)&v,     g_v);
    cudaGetSymbolAddress((void**)&x2,    g_x2);
    cudaGetSymbolAddress((void**)&kvp,   g_kv);
    cudaGetSymbolAddress((void**)&zp,    g_z);

    cudaFuncSetAttribute(mma_gemm<0>, cudaFuncAttributeMaxDynamicSharedMemorySize, SMEM_TOTAL);
    cudaFuncSetAttribute(mma_gemm<1>, cudaFuncAttributeMaxDynamicSharedMemorySize, SMEM_TOTAL);
    cudaFuncSetAttribute(mma_gemm<2>, cudaFuncAttributeMaxDynamicSharedMemorySize, SMEM_TOTAL);
    cudaFuncSetAttribute(mma_gemm<3>, cudaFuncAttributeMaxDynamicSharedMemorySize, SMEM_TOTAL);

    // 0. weight prep (transpose + bf16)
    transpose_bf16<<<dim3(32, 32), 256>>>(wq, wqt, D_, D_);
    transpose_bf16<<<dim3(32, 32), 256>>>(wk, wkt, D_, D_);
    transpose_bf16<<<dim3(32, 32), 256>>>(wv, wvt, D_, D_);
    transpose_bf16<<<dim3(32, 32), 256>>>(wo, wot, D_, D_);
    transpose_bf16<<<dim3(32, 128), 256>>>(w1, w1t, D_, FF_);
    transpose_bf16<<<dim3(128, 32), 256>>>(w2, w2t, FF_, D_);

    // 1. h2 = split(LN1(x))
    ln_split_kernel<<<M_, 256>>>(x, ln1g, ln1b, h2);

    // 2. q/k/v
    dim3 gD(D_ / GBN, M_ / GBM);
    mma_gemm<1><<<gD, 256, SMEM_TOTAL>>>(h2, wqt, D_, D_, nullptr, q, nullptr);
    mma_gemm<1><<<gD, 256, SMEM_TOTAL>>>(h2, wkt, D_, D_, nullptr, k, nullptr);
    mma_gemm<0><<<gD, 256, SMEM_TOTAL>>>(h2, wvt, D_, D_, nullptr, v, nullptr);

    // 3. kv/z per (b,h)
    kv_kernel<<<B_ * H_, 256>>>(k, v, kvp, zp);

    // 4. attn -> split bf16
    attn_kernel<<<dim3(B_ * H_, S_ / 128), 128>>>(q, kvp, zp, attn2);

    // 5. x2 = x + attn @ wo
    mma_gemm<2><<<gD, 256, SMEM_TOTAL>>>(attn2, wot, D_, D_, x, x2, nullptr);

    // 6. h2 = split(LN2(x2))
    ln_split_kernel<<<M_, 256>>>(x2, ln2g, ln2b, h2);

    // 7. a1 = split(lookup(h2 @ w1))
    dim3 gF(FF_ / GBN, M_ / GBM);
    mma_gemm<3><<<gF, 256, SMEM_TOTAL>>>(h2, w1t, D_, FF_, nullptr, nullptr, a1);

    // 8. out = x2 + a1 @ w2
    mma_gemm<2><<<gD, 256, SMEM_TOTAL>>>(a1, w2t, FF_, D_, x2, out, nullptr);
}

// round 4
// speedup vs baseline: 3.7576x; 1.1037x over previous
#include <cuda_runtime.h>
#include <cuda_bf16.h>
#include <math.h>
#include <stdint.h>

// ---------------------------------------------------------------------------
// Problem constants
// ---------------------------------------------------------------------------
#define B_  4
#define S_  2048
#define D_  1024
#define H_  16
#define DH_ 64
#define FF_ 4096
#define M_  (B_ * S_)          // 8192 rows

// ---------------------------------------------------------------------------
// Scratch (device globals)
// ---------------------------------------------------------------------------
__device__ __nv_bfloat16 g_h2[M_ * 2 * D_];          // LN output, split (hi | lo)
__device__ __nv_bfloat16 g_attn2[M_ * 2 * D_];       // attention output, split
__device__ __nv_bfloat16 g_a1[(size_t)M_ * 2 * FF_]; // lookup out, split
__device__ float g_qkv[(size_t)M_ * 3 * D_];         // fused q|k|v (phi applied to q,k)
__device__ float g_x2[M_ * D_];
__device__ float g_kv[B_ * H_ * DH_ * DH_];
__device__ float g_z[B_ * H_ * DH_];
// transposed bf16 weights (K-major rows: wt[n,k] = w[k,n])
__device__ __nv_bfloat16 g_wqkvt[3 * D_ * D_];       // fused wq|wk|wv transposed
__device__ __nv_bfloat16 g_wot[D_ * D_];
__device__ __nv_bfloat16 g_w1t[FF_ * D_];
__device__ __nv_bfloat16 g_w2t[D_ * FF_];

// ---------------------------------------------------------------------------
// PTX helpers (portable ISA: cp.async, ldmatrix, mma.sync)
// ---------------------------------------------------------------------------
__device__ __forceinline__ uint32_t smem_u32(const void* p) {
    uint32_t a;
    asm("{ .reg .u64 t; cvta.to.shared.u64 t, %1; cvt.u32.u64 %0, t; }"
        : "=r"(a) : "l"(p));
    return a;
}
__device__ __forceinline__ void cp_async16(uint32_t dst, const void* src) {
    asm volatile("cp.async.cg.shared.global [%0], [%1], 16;" :: "r"(dst), "l"(src));
}
#define CP_COMMIT() asm volatile("cp.async.commit_group;" ::: "memory")
template <int N>
__device__ __forceinline__ void cp_wait() {
    asm volatile("cp.async.wait_group %0;" :: "n"(N) : "memory");
}
__device__ __forceinline__ void ldm_x4(uint32_t& r0, uint32_t& r1, uint32_t& r2,
                                       uint32_t& r3, uint32_t addr) {
    asm volatile("ldmatrix.sync.aligned.m8n8.x4.shared.b16 {%0,%1,%2,%3}, [%4];"
                 : "=r"(r0), "=r"(r1), "=r"(r2), "=r"(r3) : "r"(addr));
}
__device__ __forceinline__ void mma_bf16(float& c0, float& c1, float& c2, float& c3,
                                         uint32_t a0, uint32_t a1, uint32_t a2,
                                         uint32_t a3, uint32_t b0, uint32_t b1) {
    asm volatile(
        "mma.sync.aligned.m16n8k16.row.col.f32.bf16.bf16.f32 "
        "{%0,%1,%2,%3}, {%4,%5,%6,%7}, {%8,%9}, {%0,%1,%2,%3};"
        : "+f"(c0), "+f"(c1), "+f"(c2), "+f"(c3)
        : "r"(a0), "r"(a1), "r"(a2), "r"(a3), "r"(b0), "r"(b1));
}
__device__ __forceinline__ uint32_t swz(uint32_t o) { return o ^ ((o >> 3) & 0x70u); }

// ---------------------------------------------------------------------------
// Math helpers
// ---------------------------------------------------------------------------
__device__ __forceinline__ float phi_fn(float v) {
    return v > 0.0f ? v + 1.0f : expf(v);
}
__device__ __forceinline__ float lookup_gelu(float v) {
    float r = rintf(__fdiv_rn(v, 0.1f));
    r = fminf(fmaxf(r, -128.0f), 127.0f);
    float xq = r * 0.1f;
    float inner = 0.7978845608028654f * (xq + 0.044715f * xq * xq * xq);
    return 0.5f * xq * (1.0f + tanhf(inner));
}
__device__ __forceinline__ void split_bf16(float v, __nv_bfloat16& hi, __nv_bfloat16& lo) {
    hi = __float2bfloat16_rn(v);
    lo = __float2bfloat16_rn(v - __bfloat162float(hi));
}

// ---------------------------------------------------------------------------
// bf16 split GEMM via mma.sync:
//   C[M,Ntot] = Ahi @ W^T + Alo @ W^T
//   A2 bf16 [M, 2K] (hi | lo), Bt bf16 [Ntot, K] (K-major)
// Tile 128x256, BK=64, 3-stage cp.async, 256 threads, warp tile 64x64.
// EPI: 1 phi for cols<phiN else identity (->f32), 2 +res->f32,
//      3 lookup->bf16 split
// ---------------------------------------------------------------------------
#define GBM 128
#define GBN 256
#define KC  64                        // bf16 elements per k-chunk (128 bytes)
#define TILE_B  (GBN * 128)           // 32 KB
#define TILE_A  (GBM * 128)           // 16 KB
#define STG_BYTES (TILE_B + 2 * TILE_A)   // 64 KB
#define OFF_B  0
#define OFF_AH TILE_B
#define OFF_AL (TILE_B + TILE_A)
#define NSTG 3
#define SMEM_TOTAL (NSTG * STG_BYTES)  // 192 KB

template <int EPI>
__global__ __launch_bounds__(256, 1)
void mma_gemm(const __nv_bfloat16* __restrict__ A2, const __nv_bfloat16* __restrict__ Bt,
              int K, int Ntot, int phiN, const float* __restrict__ res,
              float* __restrict__ outF, __nv_bfloat16* __restrict__ outS)
{
    extern __shared__ char smem[];
    const uint32_t sb = smem_u32(smem);
    const int tid = threadIdx.x;
    const int wid = tid >> 5;
    const int lane = tid & 31;
    const int wr = wid >> 2;          // 0..1 : warp row (64 rows)
    const int wc = wid & 3;           // 0..3 : warp col (64 cols)
    const int row0 = blockIdx.y * GBM;
    const int col0 = blockIdx.x * GBN;
    const int lda = 2 * K;
    const int C = K / KC;

    const int g = lane >> 3;
    const int l8 = lane & 7;
    const int a_row = wr * 64 + (g & 1) * 8 + l8;
    const int a_kb  = (g >> 1) * 16;
    const int b_row = wc * 64 + (g >> 1) * 8 + l8;
    const int b_kb  = (g & 1) * 16;

    float acc[4][8][4];
    #pragma unroll
    for (int i = 0; i < 4; i++)
        #pragma unroll
        for (int j = 0; j < 8; j++)
            #pragma unroll
            for (int t = 0; t < 4; t++) acc[i][j][t] = 0.0f;

    auto load_chunk = [&](int c, int s) {
        const uint32_t st = sb + s * STG_BYTES;
        const int k0 = c * KC;
        // B: 256 rows x 8 16B segs = 2048 -> 8 per thread
        #pragma unroll
        for (int i = 0; i < 8; ++i) {
            int seg = i * 256 + tid;
            int r = seg >> 3, c8 = seg & 7;
            cp_async16(st + OFF_B + swz(r * 128 + c8 * 16),
                       Bt + (size_t)(col0 + r) * K + k0 + c8 * 8);
        }
        // A hi/lo: 128 rows x 8 segs = 1024 -> 4 per thread each
        #pragma unroll
        for (int i = 0; i < 4; ++i) {
            int seg = i * 256 + tid;
            int r = seg >> 3, c8 = seg & 7;
            uint32_t doff = swz(r * 128 + c8 * 16);
            const __nv_bfloat16* ah = A2 + (size_t)(row0 + r) * lda + k0 + c8 * 8;
            cp_async16(st + OFF_AH + doff, ah);
            cp_async16(st + OFF_AL + doff, ah + K);
        }
        CP_COMMIT();
    };

    load_chunk(0, 0);
    if (C > 1) load_chunk(1, 1);
    if (C > 2) load_chunk(2, 2);

    for (int c = 0; c < C; ++c) {
        const int s = c % NSTG;
        if (c + 3 <= C) cp_wait<2>();
        else if (c + 2 == C) cp_wait<1>();
        else cp_wait<0>();
        __syncthreads();

        const uint32_t st = sb + s * STG_BYTES;
        const uint32_t ahb = st + OFF_AH;
        const uint32_t alb = st + OFF_AL;
        const uint32_t bbb = st + OFF_B;

        #pragma unroll
        for (int ks = 0; ks < 4; ++ks) {
            const int kb = ks * 32;
            // B fragments: 8 n-atoms (4 x ldmatrix.x4)
            uint32_t bf[8][2];
            #pragma unroll
            for (int nb = 0; nb < 4; ++nb) {
                uint32_t addr = bbb + swz((b_row + nb * 16) * 128 + kb + b_kb);
                ldm_x4(bf[nb * 2][0], bf[nb * 2][1],
                       bf[nb * 2 + 1][0], bf[nb * 2 + 1][1], addr);
            }
            // A hi
            #pragma unroll
            for (int ma = 0; ma < 4; ++ma) {
                uint32_t a0, a1, a2, a3;
                ldm_x4(a0, a1, a2, a3,
                       ahb + swz((a_row + ma * 16) * 128 + kb + a_kb));
                #pragma unroll
                for (int na = 0; na < 8; ++na)
                    mma_bf16(acc[ma][na][0], acc[ma][na][1],
                             acc[ma][na][2], acc[ma][na][3],
                             a0, a1, a2, a3, bf[na][0], bf[na][1]);
            }
            // A lo
            #pragma unroll
            for (int ma = 0; ma < 4; ++ma) {
                uint32_t a0, a1, a2, a3;
                ldm_x4(a0, a1, a2, a3,
                       alb + swz((a_row + ma * 16) * 128 + kb + a_kb));
                #pragma unroll
                for (int na = 0; na < 8; ++na)
                    mma_bf16(acc[ma][na][0], acc[ma][na][1],
                             acc[ma][na][2], acc[ma][na][3],
                             a0, a1, a2, a3, bf[na][0], bf[na][1]);
            }
        }
        __syncthreads();
        if (c + 3 < C) load_chunk(c + 3, s);
    }

    // Epilogue
    const int er = row0 + wr * 64 + (lane >> 2);
    const int ec = col0 + wc * 64 + (lane & 3) * 2;
    #pragma unroll
    for (int ma = 0; ma < 4; ++ma) {
        #pragma unroll
        for (int na = 0; na < 8; ++na) {
            const int r0r = er + ma * 16;
            const int cc = ec + na * 8;
            if (EPI == 3) {
                #pragma unroll
                for (int half = 0; half < 2; ++half) {
                    const int rr = r0r + half * 8;
                    float v0 = lookup_gelu(acc[ma][na][half * 2 + 0]);
                    float v1 = lookup_gelu(acc[ma][na][half * 2 + 1]);
                    __nv_bfloat16 h0, l0, h1, l1;
                    split_bf16(v0, h0, l0);
                    split_bf16(v1, h1, l1);
                    __nv_bfloat162 hp; hp.x = h0; hp.y = h1;
                    __nv_bfloat162 lp; lp.x = l0; lp.y = l1;
                    size_t base = (size_t)rr * (2 * Ntot) + cc;
                    *reinterpret_cast<__nv_bfloat162*>(outS + base) = hp;
                    *reinterpret_cast<__nv_bfloat162*>(outS + base + Ntot) = lp;
                }
            } else {
                #pragma unroll
                for (int half = 0; half < 2; ++half) {
                    const int rr = r0r + half * 8;
                    float v0 = acc[ma][na][half * 2 + 0];
                    float v1 = acc[ma][na][half * 2 + 1];
                    if (EPI == 1 && cc < phiN) { v0 = phi_fn(v0); v1 = phi_fn(v1); }
                    float* op = outF + (size_t)rr * Ntot + cc;
                    if (EPI == 2) {
                        const float2 rv = *reinterpret_cast<const float2*>(
                            res + (size_t)rr * Ntot + cc);
                        v0 += rv.x; v1 += rv.y;
                    }
                    float2 o; o.x = v0; o.y = v1;
                    *reinterpret_cast<float2*>(op) = o;
                }
            }
        }
    }
}

// ---------------------------------------------------------------------------
// Weight transpose + bf16 convert: wt[n,k] = bf16(w[k,n])
// ---------------------------------------------------------------------------
__global__ __launch_bounds__(256)
void transpose_bf16(const float* __restrict__ w, __nv_bfloat16* __restrict__ wt,
                    int K, int N)
{
    __shared__ float t[32][33];
    const int tx = threadIdx.x & 31, ty = threadIdx.x >> 5;  // 32 x 8
    const int k0 = blockIdx.x * 32, n0 = blockIdx.y * 32;
    #pragma unroll
    for (int i = 0; i < 4; ++i)
        t[ty + i * 8][tx] = w[(size_t)(k0 + ty + i * 8) * N + n0 + tx];
    __syncthreads();
    #pragma unroll
    for (int i = 0; i < 4; ++i)
        wt[(size_t)(n0 + ty + i * 8) * K + k0 + tx] =
            __float2bfloat16_rn(t[tx][ty + i * 8]);
}

// ---------------------------------------------------------------------------
// LayerNorm -> split bf16 [M, 2*D]
// ---------------------------------------------------------------------------
__global__ __launch_bounds__(256)
void ln_split_kernel(const float* __restrict__ x, const float* __restrict__ g,
                     const float* __restrict__ bb, __nv_bfloat16* __restrict__ y2)
{
    __shared__ float red[8];
    const int row = blockIdx.x;
    const int tid = threadIdx.x;
    float4 v = reinterpret_cast<const float4*>(x + (size_t)row * D_)[tid];

    float s = v.x + v.y + v.z + v.w;
    #pragma unroll
    for (int o = 16; o > 0; o >>= 1) s += __shfl_xor_sync(0xffffffffu, s, o);
    if ((tid & 31) == 0) red[tid >> 5] = s;
    __syncthreads();
    s = 0.0f;
    #pragma unroll
    for (int i = 0; i < 8; i++) s += red[i];
    const float mean = s * (1.0f / D_);
    __syncthreads();

    float d0 = v.x - mean, d1 = v.y - mean, d2 = v.z - mean, d3 = v.w - mean;
    float s2 = d0 * d0 + d1 * d1 + d2 * d2 + d3 * d3;
    #pragma unroll
    for (int o = 16; o > 0; o >>= 1) s2 += __shfl_xor_sync(0xffffffffu, s2, o);
    if ((tid & 31) == 0) red[tid >> 5] = s2;
    __syncthreads();
    s2 = 0.0f;
    #pragma unroll
    for (int i = 0; i < 8; i++) s2 += red[i];
    const float rs = rsqrtf(s2 * (1.0f / D_) + 1e-5f);

    float4 gg = reinterpret_cast<const float4*>(g)[tid];
    float4 bv = reinterpret_cast<const float4*>(bb)[tid];
    float o0 = d0 * rs * gg.x + bv.x;
    float o1 = d1 * rs * gg.y + bv.y;
    float o2 = d2 * rs * gg.z + bv.z;
    float o3 = d3 * rs * gg.w + bv.w;

    size_t base = (size_t)row * (2 * D_) + tid * 4;
    __nv_bfloat16 h0, l0, h1, l1, h2, l2, h3, l3;
    split_bf16(o0, h0, l0); split_bf16(o1, h1, l1);
    split_bf16(o2, h2, l2); split_bf16(o3, h3, l3);
    __nv_bfloat162 hp0; hp0.x = h0; hp0.y = h1;
    __nv_bfloat162 hp1; hp1.x = h2; hp1.y = h3;
    __nv_bfloat162 lp0; lp0.x = l0; lp0.y = l1;
    __nv_bfloat162 lp1; lp1.x = l2; lp1.y = l3;
    *reinterpret_cast<__nv_bfloat162*>(y2 + base) = hp0;
    *reinterpret_cast<__nv_bfloat162*>(y2 + base + 2) = hp1;
    *reinterpret_cast<__nv_bfloat162*>(y2 + base + D_) = lp0;
    *reinterpret_cast<__nv_bfloat162*>(y2 + base + D_ + 2) = lp1;
}

// ---------------------------------------------------------------------------
// kv[b,h,d,e] = sum_s phi_k * v ; z[b,h,d] = sum_s phi_k
// reads from fused qkv buffer [M, 3D]: k at +D, v at +2D
// ---------------------------------------------------------------------------
#define QKV_LD (3 * D_)
__global__ __launch_bounds__(256)
void kv_kernel(const float* __restrict__ qkv,
               float* __restrict__ kv, float* __restrict__ z)
{
    const int bh = blockIdx.x;
    const int b = bh >> 4, h = bh & 15;
    const float* Kp = qkv + (size_t)b * S_ * QKV_LD + D_ + h * DH_;
    const float* Vp = qkv + (size_t)b * S_ * QKV_LD + 2 * D_ + h * DH_;

    __shared__ float Ks[32][DH_];
    __shared__ float Vs[32][DH_];

    const int tid = threadIdx.x;
    const int tx = tid & 15, ty = tid >> 4;

    float acc[4][4];
    #pragma unroll
    for (int i = 0; i < 4; i++)
        #pragma unroll
        for (int j = 0; j < 4; j++) acc[i][j] = 0.0f;
    float zacc = 0.0f;

    for (int s0 = 0; s0 < S_; s0 += 32) {
        #pragma unroll
        for (int i = 0; i < 2; i++) {
            int jj = tid * 2 + i;
            int r = jj >> 4, c4 = jj & 15;
            *reinterpret_cast<float4*>(&Ks[r][c4 * 4]) =
                *reinterpret_cast<const float4*>(&Kp[(size_t)(s0 + r) * QKV_LD + c4 * 4]);
            *reinterpret_cast<float4*>(&Vs[r][c4 * 4]) =
                *reinterpret_cast<const float4*>(&Vp[(size_t)(s0 + r) * QKV_LD + c4 * 4]);
        }
        __syncthreads();
        #pragma unroll 8
        for (int s = 0; s < 32; s++) {
            float a[4], bv[4];
            *reinterpret_cast<float4*>(a) = *reinterpret_cast<const float4*>(&Ks[s][ty * 4]);
            *reinterpret_cast<float4*>(bv) = *reinterpret_cast<const float4*>(&Vs[s][tx * 4]);
            #pragma unroll
            for (int i = 0; i < 4; i++)
                #pragma unroll
                for (int j = 0; j < 4; j++) acc[i][j] += a[i] * bv[j];
        }
        if (tid < DH_) {
            #pragma unroll 8
            for (int s = 0; s < 32; s++) zacc += Ks[s][tid];
        }
        __syncthreads();
    }

    float* kvp = kv + (size_t)bh * DH_ * DH_;
    #pragma unroll
    for (int i = 0; i < 4; i++)
        #pragma unroll
        for (int j = 0; j < 4; j++)
            kvp[(ty * 4 + i) * DH_ + tx * 4 + j] = acc[i][j];
    if (tid < DH_) z[bh * DH_ + tid] = zacc;
}

// ---------------------------------------------------------------------------
// attn out row = (phi_q @ kv) / (phi_q . z + 1e-6)  -> split bf16 [M, 2*D]
// q read from fused qkv buffer (offset 0, stride 3D)
// ---------------------------------------------------------------------------
__global__ __launch_bounds__(128)
void attn_kernel(const float* __restrict__ qkv, const float* __restrict__ kv,
                 const float* __restrict__ z, __nv_bfloat16* __restrict__ out2)
{
    const int bh = blockIdx.x;
    const int b = bh >> 4, h = bh & 15;
    __shared__ float kvs[DH_ * DH_];
    __shared__ float zs[DH_];
    const int tid = threadIdx.x;

    const float4* kvg = reinterpret_cast<const float4*>(kv + (size_t)bh * DH_ * DH_);
    #pragma unroll
    for (int i = 0; i < 8; i++)
        reinterpret_cast<float4*>(kvs)[tid + i * 128] = kvg[tid + i * 128];
    if (tid < 16)
        reinterpret_cast<float4*>(zs)[tid] =
            reinterpret_cast<const float4*>(z + bh * DH_)[tid];
    __syncthreads();

    const int s = blockIdx.y * 128 + tid;
    const float* qr = qkv + (size_t)(b * S_ + s) * QKV_LD + h * DH_;
    float pq[DH_];
    #pragma unroll
    for (int i = 0; i < 16; i++)
        reinterpret_cast<float4*>(pq)[i] = reinterpret_cast<const float4*>(qr)[i];

    float acc[DH_];
    #pragma unroll
    for (int e = 0; e < DH_; e++) acc[e] = 0.0f;
    float den = 1e-6f;

    #pragma unroll 8
    for (int d = 0; d < DH_; d++) {
        float a = pq[d];
        den += a * zs[d];
        const float4* kr = reinterpret_cast<const float4*>(&kvs[d * DH_]);
        #pragma unroll
        for (int e4 = 0; e4 < 16; e4++) {
            float4 kk = kr[e4];
            acc[e4 * 4 + 0] += a * kk.x;
            acc[e4 * 4 + 1] += a * kk.y;
            acc[e4 * 4 + 2] += a * kk.z;
            acc[e4 * 4 + 3] += a * kk.w;
        }
    }

    const float inv = __fdiv_rn(1.0f, den);
    size_t base = (size_t)(b * S_ + s) * (2 * D_) + h * DH_;
    #pragma unroll
    for (int e = 0; e < DH_; e += 2) {
        __nv_bfloat16 h0, l0, h1, l1;
        split_bf16(acc[e] * inv, h0, l0);
        split_bf16(acc[e + 1] * inv, h1, l1);
        __nv_bfloat162 hp; hp.x = h0; hp.y = h1;
        __nv_bfloat162 lp; lp.x = l0; lp.y = l1;
        *reinterpret_cast<__nv_bfloat162*>(out2 + base + e) = hp;
        *reinterpret_cast<__nv_bfloat162*>(out2 + base + D_ + e) = lp;
    }
}

// ---------------------------------------------------------------------------
// Launch
// ---------------------------------------------------------------------------
extern "C" void kernel_launch(void* const* d_in, const int* in_sizes, int n_in,
                              void* d_out, int out_size)
{
    const float* x    = (const float*)d_in[0];
    const float* ln1g = (const float*)d_in[1];
    const float* ln1b = (const float*)d_in[2];
    const float* wq   = (const float*)d_in[3];
    const float* wk   = (const float*)d_in[4];
    const float* wv   = (const float*)d_in[5];
    const float* wo   = (const float*)d_in[6];
    const float* ln2g = (const float*)d_in[7];
    const float* ln2b = (const float*)d_in[8];
    const float* w1   = (const float*)d_in[9];
    const float* w2   = (const float*)d_in[10];
    float* out = (float*)d_out;

    __nv_bfloat16 *h2, *attn2, *a1, *wqkvt, *wot, *w1t, *w2t;
    float *qkv, *x2, *kvp, *zp;
    cudaGetSymbolAddress((void**)&h2,    g_h2);
    cudaGetSymbolAddress((void**)&attn2, g_attn2);
    cudaGetSymbolAddress((void**)&a1,    g_a1);
    cudaGetSymbolAddress((void**)&wqkvt, g_wqkvt);
    cudaGetSymbolAddress((void**)&wot,   g_wot);
    cudaGetSymbolAddress((void**)&w1t,   g_w1t);
    cudaGetSymbolAddress((void**)&w2t,   g_w2t);
    cudaGetSymbolAddress((void**)&qkv,   g_qkv);
    cudaGetSymbolAddress((void**)&x2,    g_x2);
    cudaGetSymbolAddress((void**)&kvp,   g_kv);
    cudaGetSymbolAddress((void**)&zp,    g_z);

    cudaFuncSetAttribute(mma_gemm<1>, cudaFuncAttributeMaxDynamicSharedMemorySize, SMEM_TOTAL);
    cudaFuncSetAttribute(mma_gemm<2>, cudaFuncAttributeMaxDynamicSharedMemorySize, SMEM_TOTAL);
    cudaFuncSetAttribute(mma_gemm<3>, cudaFuncAttributeMaxDynamicSharedMemorySize, SMEM_TOTAL);

    // 0. weight prep (transpose + bf16); q|k|v fused into one [3D, D] buffer
    transpose_bf16<<<dim3(32, 32), 256>>>(wq, wqkvt, D_, D_);
    transpose_bf16<<<dim3(32, 32), 256>>>(wk, wqkvt + D_ * D_, D_, D_);
    transpose_bf16<<<dim3(32, 32), 256>>>(wv, wqkvt + 2 * D_ * D_, D_, D_);
    transpose_bf16<<<dim3(32, 32), 256>>>(wo, wot, D_, D_);
    transpose_bf16<<<dim3(32, 128), 256>>>(w1, w1t, D_, FF_);
    transpose_bf16<<<dim3(128, 32), 256>>>(w2, w2t, FF_, D_);

    // 1. h2 = split(LN1(x))
    ln_split_kernel<<<M_, 256>>>(x, ln1g, ln1b, h2);

    // 2. fused qkv = h2 @ [wq|wk|wv]; phi for cols < 2D (q,k)
    dim3 gQKV(3 * D_ / GBN, M_ / GBM);
    mma_gemm<1><<<gQKV, 256, SMEM_TOTAL>>>(h2, wqkvt, D_, 3 * D_, 2 * D_,
                                           nullptr, qkv, nullptr);

    // 3. kv/z per (b,h)
    kv_kernel<<<B_ * H_, 256>>>(qkv, kvp, zp);

    // 4. attn -> split bf16
    attn_kernel<<<dim3(B_ * H_, S_ / 128), 128>>>(qkv, kvp, zp, attn2);

    // 5. x2 = x + attn @ wo
    dim3 gD(D_ / GBN, M_ / GBM);
    mma_gemm<2><<<gD, 256, SMEM_TOTAL>>>(attn2, wot, D_, D_, 0, x, x2, nullptr);

    // 6. h2 = split(LN2(x2))
    ln_split_kernel<<<M_, 256>>>(x2, ln2g, ln2b, h2);

    // 7. a1 = split(lookup(h2 @ w1))
    dim3 gF(FF_ / GBN, M_ / GBM);
    mma_gemm<3><<<gF, 256, SMEM_TOTAL>>>(h2, w1t, D_, FF_, 0, nullptr, nullptr, a1);

    // 8. out = x2 + a1 @ w2
    mma_gemm<2><<<gD, 256, SMEM_TOTAL>>>(a1, w2t, FF_, D_, 0, x2, out, nullptr);
}

// round 5
// speedup vs baseline: 4.4914x; 1.1953x over previous
#include <cuda_runtime.h>
#include <cuda_fp16.h>
#include <math.h>
#include <stdint.h>

// ---------------------------------------------------------------------------
// Problem constants
// ---------------------------------------------------------------------------
#define B_  4
#define S_  2048
#define D_  1024
#define H_  16
#define DH_ 64
#define FF_ 4096
#define M_  (B_ * S_)          // 8192 rows
#define KVCH 8                 // kv reduction S-chunks

// ---------------------------------------------------------------------------
// Scratch (device globals)
// ---------------------------------------------------------------------------
__device__ __half g_h2[M_ * 2 * D_];            // LN output, split (hi | lo)
__device__ __half g_attn2[M_ * 2 * D_];         // attention output, split
__device__ __half g_a1[(size_t)M_ * FF_];       // lookup out, fp16 single
__device__ float g_qkv[(size_t)M_ * 3 * D_];    // fused q|k|v (phi on q,k)
__device__ float g_x2[M_ * D_];
__device__ float g_kv[B_ * H_ * DH_ * DH_];
__device__ float g_z[B_ * H_ * DH_];
__device__ float g_kvpart[KVCH * B_ * H_ * DH_ * DH_];
__device__ float g_zpart[KVCH * B_ * H_ * DH_];
// transposed fp16 weights (K-major rows: wt[n,k] = w[k,n])
__device__ __half g_wqkvt[3 * D_ * D_];
__device__ __half g_wot[D_ * D_];
__device__ __half g_w1t[FF_ * D_];
__device__ __half g_w2t[D_ * FF_];

// ---------------------------------------------------------------------------
// PTX helpers (portable ISA: cp.async, ldmatrix, mma.sync)
// ---------------------------------------------------------------------------
__device__ __forceinline__ uint32_t smem_u32(const void* p) {
    uint32_t a;
    asm("{ .reg .u64 t; cvta.to.shared.u64 t, %1; cvt.u32.u64 %0, t; }"
        : "=r"(a) : "l"(p));
    return a;
}
__device__ __forceinline__ void cp_async16(uint32_t dst, const void* src) {
    asm volatile("cp.async.cg.shared.global [%0], [%1], 16;" :: "r"(dst), "l"(src));
}
#define CP_COMMIT() asm volatile("cp.async.commit_group;" ::: "memory")
template <int N>
__device__ __forceinline__ void cp_wait() {
    asm volatile("cp.async.wait_group %0;" :: "n"(N) : "memory");
}
__device__ __forceinline__ void ldm_x4(uint32_t& r0, uint32_t& r1, uint32_t& r2,
                                       uint32_t& r3, uint32_t addr) {
    asm volatile("ldmatrix.sync.aligned.m8n8.x4.shared.b16 {%0,%1,%2,%3}, [%4];"
                 : "=r"(r0), "=r"(r1), "=r"(r2), "=r"(r3) : "r"(addr));
}
__device__ __forceinline__ void mma_f16(float& c0, float& c1, float& c2, float& c3,
                                        uint32_t a0, uint32_t a1, uint32_t a2,
                                        uint32_t a3, uint32_t b0, uint32_t b1) {
    asm volatile(
        "mma.sync.aligned.m16n8k16.row.col.f32.f16.f16.f32 "
        "{%0,%1,%2,%3}, {%4,%5,%6,%7}, {%8,%9}, {%0,%1,%2,%3};"
        : "+f"(c0), "+f"(c1), "+f"(c2), "+f"(c3)
        : "r"(a0), "r"(a1), "r"(a2), "r"(a3), "r"(b0), "r"(b1));
}
__device__ __forceinline__ uint32_t swz(uint32_t o) { return o ^ ((o >> 3) & 0x70u); }

// ---------------------------------------------------------------------------
// Math helpers
// ---------------------------------------------------------------------------
__device__ __forceinline__ float phi_fn(float v) {
    return v > 0.0f ? v + 1.0f : expf(v);
}
__device__ __forceinline__ float lookup_gelu(float v) {
    float r = rintf(__fdiv_rn(v, 0.1f));
    r = fminf(fmaxf(r, -128.0f), 127.0f);
    float xq = r * 0.1f;
    float inner = 0.7978845608028654f * (xq + 0.044715f * xq * xq * xq);
    return 0.5f * xq * (1.0f + tanhf(inner));
}
__device__ __forceinline__ void split_f16(float v, __half& hi, __half& lo) {
    hi = __float2half_rn(v);
    lo = __float2half_rn(v - __half2float(hi));
}

// ---------------------------------------------------------------------------
// fp16 GEMM via mma.sync:
//   NA=2: C = Ahi @ W^T + Alo @ W^T, A2 fp16 [M, 2K] (hi | lo)
//   NA=1: C = A @ W^T,               A2 fp16 [M, K]
//   Bt fp16 [Ntot, K] (K-major)
// Tile 128x256, BK=64, 3-stage cp.async, 256 threads, warp tile 64x64.
// EPI: 1 phi for cols<phiN else identity (->f32), 2 +res->f32,
//      3 lookup->fp16 single
// ---------------------------------------------------------------------------
#define GBM 128
#define GBN 256
#define KC  64
#define TILE_B  (GBN * 128)           // 32 KB
#define TILE_A  (GBM * 128)           // 16 KB
#define NSTG 3
#define OFF_B  0
#define OFF_AH TILE_B
#define OFF_AL (TILE_B + TILE_A)
#define STG_BYTES_(NA)  (TILE_B + (NA) * TILE_A)
#define SMEM_TOTAL_(NA) (NSTG * STG_BYTES_(NA))

template <int EPI, int NA>
__global__ __launch_bounds__(256, 1)
void mma_gemm(const __half* __restrict__ A2, const __half* __restrict__ Bt,
              int K, int Ntot, int phiN, const float* __restrict__ res,
              float* __restrict__ outF, __half* __restrict__ outS)
{
    constexpr int STG_BYTES = STG_BYTES_(NA);
    extern __shared__ char smem[];
    const uint32_t sb = smem_u32(smem);
    const int tid = threadIdx.x;
    const int wid = tid >> 5;
    const int lane = tid & 31;
    const int wr = wid >> 2;
    const int wc = wid & 3;
    const int row0 = blockIdx.y * GBM;
    const int col0 = blockIdx.x * GBN;
    const int lda = NA * K;
    const int C = K / KC;

    const int g = lane >> 3;
    const int l8 = lane & 7;
    const int a_row = wr * 64 + (g & 1) * 8 + l8;
    const int a_kb  = (g >> 1) * 16;
    const int b_row = wc * 64 + (g >> 1) * 8 + l8;
    const int b_kb  = (g & 1) * 16;

    float acc[4][8][4];
    #pragma unroll
    for (int i = 0; i < 4; i++)
        #pragma unroll
        for (int j = 0; j < 8; j++)
            #pragma unroll
            for (int t = 0; t < 4; t++) acc[i][j][t] = 0.0f;

    auto load_chunk = [&](int c, int s) {
        const uint32_t st = sb + s * STG_BYTES;
        const int k0 = c * KC;
        #pragma unroll
        for (int i = 0; i < 8; ++i) {
            int seg = i * 256 + tid;
            int r = seg >> 3, c8 = seg & 7;
            cp_async16(st + OFF_B + swz(r * 128 + c8 * 16),
                       Bt + (size_t)(col0 + r) * K + k0 + c8 * 8);
        }
        #pragma unroll
        for (int i = 0; i < 4; ++i) {
            int seg = i * 256 + tid;
            int r = seg >> 3, c8 = seg & 7;
            uint32_t doff = swz(r * 128 + c8 * 16);
            const __half* ah = A2 + (size_t)(row0 + r) * lda + k0 + c8 * 8;
            cp_async16(st + OFF_AH + doff, ah);
            if (NA == 2) cp_async16(st + OFF_AL + doff, ah + K);
        }
        CP_COMMIT();
    };

    load_chunk(0, 0);
    if (C > 1) load_chunk(1, 1);
    if (C > 2) load_chunk(2, 2);

    for (int c = 0; c < C; ++c) {
        const int s = c % NSTG;
        if (c + 3 <= C) cp_wait<2>();
        else if (c + 2 == C) cp_wait<1>();
        else cp_wait<0>();
        __syncthreads();

        const uint32_t st = sb + s * STG_BYTES;
        const uint32_t ahb = st + OFF_AH;
        const uint32_t alb = st + OFF_AL;
        const uint32_t bbb = st + OFF_B;

        #pragma unroll
        for (int ks = 0; ks < 4; ++ks) {
            const int kb = ks * 32;
            uint32_t bf[8][2];
            #pragma unroll
            for (int nb = 0; nb < 4; ++nb) {
                uint32_t addr = bbb + swz((b_row + nb * 16) * 128 + kb + b_kb);
                ldm_x4(bf[nb * 2][0], bf[nb * 2][1],
                       bf[nb * 2 + 1][0], bf[nb * 2 + 1][1], addr);
            }
            #pragma unroll
            for (int ma = 0; ma < 4; ++ma) {
                uint32_t a0, a1, a2, a3;
                ldm_x4(a0, a1, a2, a3,
                       ahb + swz((a_row + ma * 16) * 128 + kb + a_kb));
                #pragma unroll
                for (int na = 0; na < 8; ++na)
                    mma_f16(acc[ma][na][0], acc[ma][na][1],
                            acc[ma][na][2], acc[ma][na][3],
                            a0, a1, a2, a3, bf[na][0], bf[na][1]);
            }
            if (NA == 2) {
                #pragma unroll
                for (int ma = 0; ma < 4; ++ma) {
                    uint32_t a0, a1, a2, a3;
                    ldm_x4(a0, a1, a2, a3,
                           alb + swz((a_row + ma * 16) * 128 + kb + a_kb));
                    #pragma unroll
                    for (int na = 0; na < 8; ++na)
                        mma_f16(acc[ma][na][0], acc[ma][na][1],
                                acc[ma][na][2], acc[ma][na][3],
                                a0, a1, a2, a3, bf[na][0], bf[na][1]);
                }
            }
        }
        __syncthreads();
        if (c + 3 < C) load_chunk(c + 3, s);
    }

    // Epilogue
    const int er = row0 + wr * 64 + (lane >> 2);
    const int ec = col0 + wc * 64 + (lane & 3) * 2;
    #pragma unroll
    for (int ma = 0; ma < 4; ++ma) {
        #pragma unroll
        for (int na = 0; na < 8; ++na) {
            const int r0r = er + ma * 16;
            const int cc = ec + na * 8;
            #pragma unroll
            for (int half_ = 0; half_ < 2; ++half_) {
                const int rr = r0r + half_ * 8;
                float v0 = acc[ma][na][half_ * 2 + 0];
                float v1 = acc[ma][na][half_ * 2 + 1];
                if (EPI == 3) {
                    v0 = lookup_gelu(v0);
                    v1 = lookup_gelu(v1);
                    *reinterpret_cast<__half2*>(outS + (size_t)rr * Ntot + cc) =
                        __floats2half2_rn(v0, v1);
                } else {
                    if (EPI == 1 && cc < phiN) { v0 = phi_fn(v0); v1 = phi_fn(v1); }
                    if (EPI == 2) {
                        const float2 rv = *reinterpret_cast<const float2*>(
                            res + (size_t)rr * Ntot + cc);
                        v0 += rv.x; v1 += rv.y;
                    }
                    float2 o; o.x = v0; o.y = v1;
                    *reinterpret_cast<float2*>(outF + (size_t)rr * Ntot + cc) = o;
                }
            }
        }
    }
}

// ---------------------------------------------------------------------------
// Weight transpose + fp16 convert: wt[n,k] = fp16(w[k,n])
// ---------------------------------------------------------------------------
__global__ __launch_bounds__(256)
void transpose_f16(const float* __restrict__ w, __half* __restrict__ wt,
                   int K, int N)
{
    __shared__ float t[32][33];
    const int tx = threadIdx.x & 31, ty = threadIdx.x >> 5;
    const int k0 = blockIdx.x * 32, n0 = blockIdx.y * 32;
    #pragma unroll
    for (int i = 0; i < 4; ++i)
        t[ty + i * 8][tx] = w[(size_t)(k0 + ty + i * 8) * N + n0 + tx];
    __syncthreads();
    #pragma unroll
    for (int i = 0; i < 4; ++i)
        wt[(size_t)(n0 + ty + i * 8) * K + k0 + tx] =
            __float2half_rn(t[tx][ty + i * 8]);
}

// ---------------------------------------------------------------------------
// LayerNorm -> split fp16 [M, 2*D]
// ---------------------------------------------------------------------------
__global__ __launch_bounds__(256)
void ln_split_kernel(const float* __restrict__ x, const float* __restrict__ g,
                     const float* __restrict__ bb, __half* __restrict__ y2)
{
    __shared__ float red[8];
    const int row = blockIdx.x;
    const int tid = threadIdx.x;
    float4 v = reinterpret_cast<const float4*>(x + (size_t)row * D_)[tid];

    float s = v.x + v.y + v.z + v.w;
    #pragma unroll
    for (int o = 16; o > 0; o >>= 1) s += __shfl_xor_sync(0xffffffffu, s, o);
    if ((tid & 31) == 0) red[tid >> 5] = s;
    __syncthreads();
    s = 0.0f;
    #pragma unroll
    for (int i = 0; i < 8; i++) s += red[i];
    const float mean = s * (1.0f / D_);
    __syncthreads();

    float d0 = v.x - mean, d1 = v.y - mean, d2 = v.z - mean, d3 = v.w - mean;
    float s2 = d0 * d0 + d1 * d1 + d2 * d2 + d3 * d3;
    #pragma unroll
    for (int o = 16; o > 0; o >>= 1) s2 += __shfl_xor_sync(0xffffffffu, s2, o);
    if ((tid & 31) == 0) red[tid >> 5] = s2;
    __syncthreads();
    s2 = 0.0f;
    #pragma unroll
    for (int i = 0; i < 8; i++) s2 += red[i];
    const float rs = rsqrtf(s2 * (1.0f / D_) + 1e-5f);

    float4 gg = reinterpret_cast<const float4*>(g)[tid];
    float4 bv = reinterpret_cast<const float4*>(bb)[tid];
    float o0 = d0 * rs * gg.x + bv.x;
    float o1 = d1 * rs * gg.y + bv.y;
    float o2 = d2 * rs * gg.z + bv.z;
    float o3 = d3 * rs * gg.w + bv.w;

    size_t base = (size_t)row * (2 * D_) + tid * 4;
    __half h0, l0, h1, l1, h2, l2, h3, l3;
    split_f16(o0, h0, l0); split_f16(o1, h1, l1);
    split_f16(o2, h2, l2); split_f16(o3, h3, l3);
    __half2 hp0; hp0.x = h0; hp0.y = h1;
    __half2 hp1; hp1.x = h2; hp1.y = h3;
    __half2 lp0; lp0.x = l0; lp0.y = l1;
    __half2 lp1; lp1.x = l2; lp1.y = l3;
    *reinterpret_cast<__half2*>(y2 + base) = hp0;
    *reinterpret_cast<__half2*>(y2 + base + 2) = hp1;
    *reinterpret_cast<__half2*>(y2 + base + D_) = lp0;
    *reinterpret_cast<__half2*>(y2 + base + D_ + 2) = lp1;
}

// ---------------------------------------------------------------------------
// kv partials: chunk ch covers S rows [ch*256, (ch+1)*256)
// kvpart[ch][bh][d][e] = sum phi_k * v ; zpart[ch][bh][d] = sum phi_k
// ---------------------------------------------------------------------------
#define QKV_LD (3 * D_)
__global__ __launch_bounds__(256)
void kv_part_kernel(const float* __restrict__ qkv,
                    float* __restrict__ kvpart, float* __restrict__ zpart)
{
    const int bh = blockIdx.x;           // 0..63
    const int ch = blockIdx.y;           // 0..KVCH-1
    const int b = bh >> 4, h = bh & 15;
    const int schunk = S_ / KVCH;        // 256
    const float* Kp = qkv + (size_t)b * S_ * QKV_LD + D_ + h * DH_
                      + (size_t)ch * schunk * QKV_LD;
    const float* Vp = Kp + D_;

    __shared__ float Ks[32][DH_];
    __shared__ float Vs[32][DH_];

    const int tid = threadIdx.x;
    const int tx = tid & 15, ty = tid >> 4;

    float acc[4][4];
    #pragma unroll
    for (int i = 0; i < 4; i++)
        #pragma unroll
        for (int j = 0; j < 4; j++) acc[i][j] = 0.0f;
    float zacc = 0.0f;

    for (int s0 = 0; s0 < schunk; s0 += 32) {
        #pragma unroll
        for (int i = 0; i < 2; i++) {
            int jj = tid * 2 + i;
            int r = jj >> 4, c4 = jj & 15;
            *reinterpret_cast<float4*>(&Ks[r][c4 * 4]) =
                *reinterpret_cast<const float4*>(&Kp[(size_t)(s0 + r) * QKV_LD + c4 * 4]);
            *reinterpret_cast<float4*>(&Vs[r][c4 * 4]) =
                *reinterpret_cast<const float4*>(&Vp[(size_t)(s0 + r) * QKV_LD + c4 * 4]);
        }
        __syncthreads();
        #pragma unroll 8
        for (int s = 0; s < 32; s++) {
            float a[4], bv[4];
            *reinterpret_cast<float4*>(a) = *reinterpret_cast<const float4*>(&Ks[s][ty * 4]);
            *reinterpret_cast<float4*>(bv) = *reinterpret_cast<const float4*>(&Vs[s][tx * 4]);
            #pragma unroll
            for (int i = 0; i < 4; i++)
                #pragma unroll
                for (int j = 0; j < 4; j++) acc[i][j] += a[i] * bv[j];
        }
        if (tid < DH_) {
            #pragma unroll 8
            for (int s = 0; s < 32; s++) zacc += Ks[s][tid];
        }
        __syncthreads();
    }

    float* kvp = kvpart + ((size_t)ch * 64 + bh) * DH_ * DH_;
    #pragma unroll
    for (int i = 0; i < 4; i++)
        #pragma unroll
        for (int j = 0; j < 4; j++)
            kvp[(ty * 4 + i) * DH_ + tx * 4 + j] = acc[i][j];
    if (tid < DH_) zpart[((size_t)ch * 64 + bh) * DH_ + tid] = zacc;
}

// Deterministic fixed-order reduce of KVCH partials
__global__ __launch_bounds__(256)
void kv_reduce_kernel(const float* __restrict__ kvpart, const float* __restrict__ zpart,
                      float* __restrict__ kv, float* __restrict__ z)
{
    const int bh = blockIdx.x;
    const int tid = threadIdx.x;
    #pragma unroll
    for (int i = 0; i < (DH_ * DH_) / 256; ++i) {
        int idx = i * 256 + tid;
        float s = 0.0f;
        #pragma unroll
        for (int ch = 0; ch < KVCH; ++ch)
            s += kvpart[((size_t)ch * 64 + bh) * DH_ * DH_ + idx];
        kv[(size_t)bh * DH_ * DH_ + idx] = s;
    }
    if (tid < DH_) {
        float s = 0.0f;
        #pragma unroll
        for (int ch = 0; ch < KVCH; ++ch)
            s += zpart[((size_t)ch * 64 + bh) * DH_ + tid];
        z[bh * DH_ + tid] = s;
    }
}

// ---------------------------------------------------------------------------
// attn out row = (phi_q @ kv) / (phi_q . z + 1e-6)  -> split fp16 [M, 2*D]
// ---------------------------------------------------------------------------
__global__ __launch_bounds__(128)
void attn_kernel(const float* __restrict__ qkv, const float* __restrict__ kv,
                 const float* __restrict__ z, __half* __restrict__ out2)
{
    const int bh = blockIdx.x;
    const int b = bh >> 4, h = bh & 15;
    __shared__ float kvs[DH_ * DH_];
    __shared__ float zs[DH_];
    const int tid = threadIdx.x;

    const float4* kvg = reinterpret_cast<const float4*>(kv + (size_t)bh * DH_ * DH_);
    #pragma unroll
    for (int i = 0; i < 8; i++)
        reinterpret_cast<float4*>(kvs)[tid + i * 128] = kvg[tid + i * 128];
    if (tid < 16)
        reinterpret_cast<float4*>(zs)[tid] =
            reinterpret_cast<const float4*>(z + bh * DH_)[tid];
    __syncthreads();

    const int s = blockIdx.y * 128 + tid;
    const float* qr = qkv + (size_t)(b * S_ + s) * QKV_LD + h * DH_;
    float pq[DH_];
    #pragma unroll
    for (int i = 0; i < 16; i++)
        reinterpret_cast<float4*>(pq)[i] = reinterpret_cast<const float4*>(qr)[i];

    float acc[DH_];
    #pragma unroll
    for (int e = 0; e < DH_; e++) acc[e] = 0.0f;
    float den = 1e-6f;

    #pragma unroll 8
    for (int d = 0; d < DH_; d++) {
        float a = pq[d];
        den += a * zs[d];
        const float4* kr = reinterpret_cast<const float4*>(&kvs[d * DH_]);
        #pragma unroll
        for (int e4 = 0; e4 < 16; e4++) {
            float4 kk = kr[e4];
            acc[e4 * 4 + 0] += a * kk.x;
            acc[e4 * 4 + 1] += a * kk.y;
            acc[e4 * 4 + 2] += a * kk.z;
            acc[e4 * 4 + 3] += a * kk.w;
        }
    }

    const float inv = __fdiv_rn(1.0f, den);
    size_t base = (size_t)(b * S_ + s) * (2 * D_) + h * DH_;
    #pragma unroll
    for (int e = 0; e < DH_; e += 2) {
        __half h0, l0, h1, l1;
        split_f16(acc[e] * inv, h0, l0);
        split_f16(acc[e + 1] * inv, h1, l1);
        __half2 hp; hp.x = h0; hp.y = h1;
        __half2 lp; lp.x = l0; lp.y = l1;
        *reinterpret_cast<__half2*>(out2 + base + e) = hp;
        *reinterpret_cast<__half2*>(out2 + base + D_ + e) = lp;
    }
}

// ---------------------------------------------------------------------------
// Launch
// ---------------------------------------------------------------------------
extern "C" void kernel_launch(void* const* d_in, const int* in_sizes, int n_in,
                              void* d_out, int out_size)
{
    const float* x    = (const float*)d_in[0];
    const float* ln1g = (const float*)d_in[1];
    const float* ln1b = (const float*)d_in[2];
    const float* wq   = (const float*)d_in[3];
    const float* wk   = (const float*)d_in[4];
    const float* wv   = (const float*)d_in[5];
    const float* wo   = (const float*)d_in[6];
    const float* ln2g = (const float*)d_in[7];
    const float* ln2b = (const float*)d_in[8];
    const float* w1   = (const float*)d_in[9];
    const float* w2   = (const float*)d_in[10];
    float* out = (float*)d_out;

    __half *h2, *attn2, *a1, *wqkvt, *wot, *w1t, *w2t;
    float *qkv, *x2, *kvp, *zp, *kvpart, *zpart;
    cudaGetSymbolAddress((void**)&h2,     g_h2);
    cudaGetSymbolAddress((void**)&attn2,  g_attn2);
    cudaGetSymbolAddress((void**)&a1,     g_a1);
    cudaGetSymbolAddress((void**)&wqkvt,  g_wqkvt);
    cudaGetSymbolAddress((void**)&wot,    g_wot);
    cudaGetSymbolAddress((void**)&w1t,    g_w1t);
    cudaGetSymbolAddress((void**)&w2t,    g_w2t);
    cudaGetSymbolAddress((void**)&qkv,    g_qkv);
    cudaGetSymbolAddress((void**)&x2,     g_x2);
    cudaGetSymbolAddress((void**)&kvp,    g_kv);
    cudaGetSymbolAddress((void**)&zp,     g_z);
    cudaGetSymbolAddress((void**)&kvpart, g_kvpart);
    cudaGetSymbolAddress((void**)&zpart,  g_zpart);

    cudaFuncSetAttribute(mma_gemm<1, 2>, cudaFuncAttributeMaxDynamicSharedMemorySize,
                         SMEM_TOTAL_(2));
    cudaFuncSetAttribute(mma_gemm<2, 2>, cudaFuncAttributeMaxDynamicSharedMemorySize,
                         SMEM_TOTAL_(2));
    cudaFuncSetAttribute(mma_gemm<3, 2>, cudaFuncAttributeMaxDynamicSharedMemorySize,
                         SMEM_TOTAL_(2));
    cudaFuncSetAttribute(mma_gemm<2, 1>, cudaFuncAttributeMaxDynamicSharedMemorySize,
                         SMEM_TOTAL_(1));

    // 0. weight prep (transpose + fp16); q|k|v fused into one [3D, D] buffer
    transpose_f16<<<dim3(32, 32), 256>>>(wq, wqkvt, D_, D_);
    transpose_f16<<<dim3(32, 32), 256>>>(wk, wqkvt + D_ * D_, D_, D_);
    transpose_f16<<<dim3(32, 32), 256>>>(wv, wqkvt + 2 * D_ * D_, D_, D_);
    transpose_f16<<<dim3(32, 32), 256>>>(wo, wot, D_, D_);
    transpose_f16<<<dim3(32, 128), 256>>>(w1, w1t, D_, FF_);
    transpose_f16<<<dim3(128, 32), 256>>>(w2, w2t, FF_, D_);

    // 1. h2 = split(LN1(x))
    ln_split_kernel<<<M_, 256>>>(x, ln1g, ln1b, h2);

    // 2. fused qkv = h2 @ [wq|wk|wv]; phi for cols < 2D (q,k)
    dim3 gQKV(3 * D_ / GBN, M_ / GBM);
    mma_gemm<1, 2><<<gQKV, 256, SMEM_TOTAL_(2)>>>(h2, wqkvt, D_, 3 * D_, 2 * D_,
                                                  nullptr, qkv, nullptr);

    // 3. kv/z partials + deterministic reduce
    kv_part_kernel<<<dim3(B_ * H_, KVCH), 256>>>(qkv, kvpart, zpart);
    kv_reduce_kernel<<<B_ * H_, 256>>>(kvpart, zpart, kvp, zp);

    // 4. attn -> split fp16
    attn_kernel<<<dim3(B_ * H_, S_ / 128), 128>>>(qkv, kvp, zp, attn2);

    // 5. x2 = x + attn @ wo
    dim3 gD(D_ / GBN, M_ / GBM);
    mma_gemm<2, 2><<<gD, 256, SMEM_TOTAL_(2)>>>(attn2, wot, D_, D_, 0, x, x2, nullptr);

    // 6. h2 = split(LN2(x2))
    ln_split_kernel<<<M_, 256>>>(x2, ln2g, ln2b, h2);

    // 7. a1 = fp16(lookup(h2 @ w1))
    dim3 gF(FF_ / GBN, M_ / GBM);
    mma_gemm<3, 2><<<gF, 256, SMEM_TOTAL_(2)>>>(h2, w1t, D_, FF_, 0, nullptr,
                                                nullptr, a1);

    // 8. out = x2 + a1 @ w2  (single fp16 A)
    mma_gemm<2, 1><<<gD, 256, SMEM_TOTAL_(1)>>>(a1, w2t, FF_, D_, 0, x2, out, nullptr);
}